// round 7
// baseline (speedup 1.0000x reference)
#include <cuda_runtime.h>

#define B        1024
#define NUM_VARS 2048
#define LEAVES   4096
#define LEVELS   12
#define WIDTH    4096
#define NINT     (LEVELS * WIDTH)          // 49152
#define TOTAL    (LEAVES + NINT)           // 53248

#define NTHR     256
#define BBK      8                  // batch columns per block
#define NBLK     (B / BBK)          // 128 blocks
#define NDISC    128                // discovery threads (warps 0-3)

#define PCAP     2048               // max needed nodes on the fast path
#define HSZ      4096               // hash slots (power of two)
#define VPAD     9
#define XPAD     2052

// Dense-fallback value buffer (only touched if the needed set exceeds PCAP).
__device__ float g_dense[(size_t)NINT * B];

// ---- smem layout (bytes) ----
#define SM_HKEY  0                               // int[HSZ]        16384
#define SM_HVAL  (SM_HKEY + HSZ * 4)             // int[HSZ]        16384
#define SM_PCH   (SM_HVAL + HSZ * 4)             // int4[PCAP]      32768
#define SM_PORIG (SM_PCH + PCAP * 16)            // int[PCAP]        8192
#define SM_POP   (SM_PORIG + PCAP * 4)           // uchar[PCAP]      2048
#define SM_DONE  (SM_POP + PCAP)                 // uint[PCAP/32]     256
#define SM_SNAP  (SM_DONE + PCAP / 8)            // uint[PCAP/32]     256
#define SM_VAL   (SM_SNAP + PCAP / 8)            // float[PCAP*VPAD] 73728
#define SM_XROW  (SM_VAL + PCAP * VPAD * 4)      // float[BBK*XPAD]  65664
#define SM_TOTAL (SM_XROW + BBK * XPAD * 4)      // ~215.7 KB

#define BAR1() asm volatile("bar.sync 1, 128;" ::: "memory")

__global__ void __launch_bounds__(NTHR, 1)
eval_all(const float* __restrict__ x,
         const int*   __restrict__ child_idx,
         const int*   __restrict__ op_type,
         float*       __restrict__ out)
{
    extern __shared__ unsigned char sm[];
    int*           hkey  = (int*)          (sm + SM_HKEY);
    int*           hval  = (int*)          (sm + SM_HVAL);
    int4*          pch   = (int4*)         (sm + SM_PCH);
    int*           porig = (int*)          (sm + SM_PORIG);
    unsigned char* pop   = (unsigned char*)(sm + SM_POP);
    unsigned int*  done  = (unsigned int*) (sm + SM_DONE);
    unsigned int*  dsnap = (unsigned int*) (sm + SM_SNAP);
    float*         val   = (float*)        (sm + SM_VAL);
    float*         xrow  = (float*)        (sm + SM_XROW);

    __shared__ int sPlanCount, sFs, sFe, sFail;

    const int tid = threadIdx.x;
    const int blk = blockIdx.x;

    if (tid < NDISC) {
        // =============== warps 0-3: BFS discovery ===============
        for (int i = tid; i < HSZ; i += NDISC) { hkey[i] = -1; hval[i] = -1; }
        BAR1();
        if (tid == 0) {
            sPlanCount = 1; sFs = 0; sFe = 1; sFail = 0;
            porig[0] = TOTAL - 1;                       // root -> plan idx 0
            const unsigned h = ((unsigned)(TOTAL - 1) * 2654435761u) & (HSZ - 1);
            hkey[h] = TOTAL - 1; hval[h] = 0;
        }
        BAR1();

        while (true) {
            const int s = sFs, e = sFe;
            if (s >= e) break;
            for (int base = s; base < e; base += NDISC) {
                const int i = base + tid;
                if (i < e) {
                    const int ni = porig[i] - LEAVES;
                    const int4 ch = ((const int4*)child_idx)[ni];
                    const int op  = op_type[ni];
                    const int cs[4] = {ch.x, ch.y, ch.z, ch.w};
                    int rc[4];
                    #pragma unroll
                    for (int f = 0; f < 4; ++f) {
                        const int c = cs[f];
                        if (c < LEAVES) { rc[f] = (int)(0x80000000u | (unsigned)c); continue; }
                        // hash insert-or-find: plan idx = compact id
                        unsigned slot = ((unsigned)c * 2654435761u) & (HSZ - 1);
                        int idx = 0; int probes = 0;
                        while (true) {
                            const int k = hkey[slot];
                            if (k == c) {                  // present: wait for idx publish
                                int v;
                                do { v = ((volatile int*)hval)[slot]; } while (v < 0);
                                idx = v; break;
                            }
                            if (k == -1) {
                                const int old = atomicCAS(&hkey[slot], -1, c);
                                if (old == -1) {           // we claimed it
                                    int id2 = atomicAdd(&sPlanCount, 1);
                                    if (id2 >= PCAP) { sFail = 1; id2 = 0; }
                                    else porig[id2] = c;
                                    hval[slot] = id2;      // publish (spinners wake)
                                    idx = id2; break;
                                }
                                if (old == c) {
                                    int v;
                                    do { v = ((volatile int*)hval)[slot]; } while (v < 0);
                                    idx = v; break;
                                }
                                // slot taken by another key: fall through to probe
                            }
                            slot = (slot + 1) & (HSZ - 1);
                            if (++probes >= HSZ) { sFail = 1; idx = 0; break; }
                        }
                        rc[f] = idx;
                    }
                    pch[i] = make_int4(rc[0], rc[1], rc[2], rc[3]);
                    pop[i] = (unsigned char)op;
                }
            }
            BAR1();
            if (tid == 0) { sFs = e; sFe = sPlanCount; }
            BAR1();
        }
    } else {
        // =============== warps 4-7: stage x rows into smem ===============
        for (int idx = tid - NDISC; idx < (BBK * NUM_VARS) / 4; idx += NTHR - NDISC) {
            const int r  = idx >> 9;              // /512 float4 per row
            const int c4 = idx & 511;
            const float4 v = ((const float4*)x)[(size_t)(blk * BBK + r) * (NUM_VARS / 4) + c4];
            *(float4*)&xrow[r * XPAD + c4 * 4] = v;
        }
    }
    __syncthreads();   // join: plan + xrow ready

    const int nplan = sPlanCount;
    const int bb    = tid & (BBK - 1);
    const int bg    = blk * BBK + bb;

    if (sFail) {
        // =============== dense fallback (worst case only) ===============
        for (int l = 0; l < LEVELS; ++l) {
            for (int k = tid; k < WIDTH * BBK; k += NTHR) {
                const int w = k >> 3, b2 = k & 7, bg2 = blk * BBK + b2;
                const int ni = l * WIDTH + w;
                const int4 ch = ((const int4*)child_idx)[ni];
                const int cs[4] = {ch.x, ch.y, ch.z, ch.w};
                float v[4];
                #pragma unroll
                for (int f = 0; f < 4; ++f) {
                    const int c = cs[f];
                    if (c < LEAVES) {
                        const float xv = xrow[b2 * XPAD + (c & (NUM_VARS - 1))];
                        v[f] = (c < NUM_VARS) ? xv : 1.0f - xv;
                    } else {
                        v[f] = g_dense[(size_t)(c - LEAVES) * B + bg2];
                    }
                }
                const float r = op_type[ni] ? (v[0] + v[1]) + (v[2] + v[3])
                                            : (v[0] * v[1]) * (v[2] * v[3]);
                g_dense[(size_t)ni * B + bg2] = r;
            }
            __syncthreads();
        }
        if (tid < BBK) out[blk * BBK + tid] = g_dense[(size_t)(NINT - 1) * B + blk * BBK + tid];
        return;
    }

    // =============== forward: dataflow ready-waves ===============
    for (int i = tid; i < PCAP / 32; i += NTHR) done[i] = 0u;
    __syncthreads();

    const int lane = tid >> 3;                    // 0..31

    for (int wave = 0; wave < 16; ++wave) {
        // snapshot done bits (readiness decided on prior waves only)
        for (int i = tid; i < PCAP / 32; i += NTHR) dsnap[i] = done[i];
        __syncthreads();

        for (int i = lane; i < nplan; i += 32) {
            if ((dsnap[i >> 5] >> (i & 31)) & 1u) continue;   // already done
            const int4 e = pch[i];
            #define RDY(c) ((c) < 0 || ((dsnap[(c) >> 5] >> ((c) & 31)) & 1u))
            if (!(RDY(e.x) && RDY(e.y) && RDY(e.z) && RDY(e.w))) continue;
            #undef RDY
            #define FETCH(c) ((c) < 0                                             \
                ? ((((c) & 0x7FFFFFFF) < NUM_VARS)                                \
                    ? xrow[bb * XPAD + ((c) & (NUM_VARS - 1))]                    \
                    : 1.0f - xrow[bb * XPAD + ((c) & (NUM_VARS - 1))])            \
                : val[(c) * VPAD + bb])
            const float v0 = FETCH(e.x);
            const float v1 = FETCH(e.y);
            const float v2 = FETCH(e.z);
            const float v3 = FETCH(e.w);
            #undef FETCH
            const float r = pop[i] ? (v0 + v1) + (v2 + v3)
                                   : (v0 * v1) * (v2 * v3);
            val[i * VPAD + bb] = r;
            if (bb == 0) atomicOr(&done[i >> 5], 1u << (i & 31));
        }
        __syncthreads();
        if (done[0] & 1u) break;                  // root computed
    }

    if (tid < BBK) out[blk * BBK + tid] = val[tid];   // root = plan idx 0
}

// ---------------------------------------------------------------------------
// Launch: x (f32), child_idx (i32), op_type (i32). One kernel; capturable.
// ---------------------------------------------------------------------------
extern "C" void kernel_launch(void* const* d_in, const int* in_sizes, int n_in,
                              void* d_out, int out_size) {
    const float* x         = (const float*)d_in[0];
    const int*   child_idx = (const int*)  d_in[1];
    const int*   op_type   = (const int*)  d_in[2];
    float*       out       = (float*)d_out;

    cudaFuncSetAttribute(eval_all,
                         cudaFuncAttributeMaxDynamicSharedMemorySize, SM_TOTAL);
    eval_all<<<NBLK, NTHR, SM_TOTAL>>>(x, child_idx, op_type, out);
}

// round 8
// speedup vs baseline: 1.8817x; 1.8817x over previous
#include <cuda_runtime.h>

#define B        1024
#define NUM_VARS 2048
#define LEAVES   4096
#define LEVELS   12
#define WIDTH    4096
#define NINT     (LEVELS * WIDTH)          // 49152
#define TOTAL    (LEAVES + NINT)           // 53248

#define NTHR     512
#define BBK      8                  // batch columns per block
#define NBLK     (B / BBK)          // 128 blocks
#define NDISC    384                // discovery threads (warps 0-11)

#define PCAP     1536               // max plan nodes on the fast path
#define HSZ      4096               // hash slots (power of two)
#define VPAD     9
#define XPAD     2052               // floats; 8208 B row stride (16B aligned)

// Dense-fallback value buffer (touched only if plan exceeds PCAP).
__device__ float g_dense[(size_t)NINT * B];

// ---- smem layout (bytes), 16B alignment where needed ----
#define SM_PCH   0                               // int4[PCAP]   raw children  24576
#define SM_SCH   (SM_PCH + PCAP * 16)            // int2[PCAP]   sorted plan   12288
#define SM_XROW  (SM_SCH + PCAP * 8)             // float[8*XPAD]              65664
#define SM_VAL   (SM_XROW + BBK * XPAD * 4)      // float[PCAP*VPAD]           55296
#define SM_HKEY  (SM_VAL + PCAP * VPAD * 4)      // int[HSZ]                   16384
#define SM_PORIG (SM_HKEY + HSZ * 4)             // int[PCAP]                   6144
#define SM_META  (SM_PORIG + PCAP * 4)           // int[PCAP] level<<16|rank    6144
#define SM_BITS  (SM_META + PCAP * 4)            // uint[NINT/32]               6144
#define SM_HVAL  (SM_BITS + NINT / 8)            // ushort[HSZ]                 8192
#define SM_SCID  (SM_HVAL + HSZ * 2)             // ushort[PCAP]                3072
#define SM_POP   (SM_SCID + PCAP * 2)            // uchar[PCAP]                 1536
#define SM_TOTAL (SM_POP + PCAP)                 // 205,440 B

#define BAR1() asm volatile("bar.sync 1, %0;" :: "n"(NDISC) : "memory")

__global__ void __launch_bounds__(NTHR, 1)
eval_all(const float* __restrict__ x,
         const int*   __restrict__ child_idx,
         const int*   __restrict__ op_type,
         float*       __restrict__ out)
{
    extern __shared__ unsigned char sm[];
    int4*           pch   = (int4*)          (sm + SM_PCH);
    int2*           sch   = (int2*)          (sm + SM_SCH);
    float*          xrow  = (float*)         (sm + SM_XROW);
    float*          val   = (float*)         (sm + SM_VAL);
    int*            hkey  = (int*)           (sm + SM_HKEY);
    int*            porig = (int*)           (sm + SM_PORIG);
    int*            meta  = (int*)           (sm + SM_META);
    unsigned int*   bits  = (unsigned int*)  (sm + SM_BITS);
    unsigned short* hval  = (unsigned short*)(sm + SM_HVAL);
    unsigned short* scid  = (unsigned short*)(sm + SM_SCID);
    unsigned char*  pop   = (unsigned char*) (sm + SM_POP);

    __shared__ int scnt, sE, sF, sFail;
    __shared__ int slcnt[LEVELS], soff[LEVELS + 1];

    const int tid = threadIdx.x;
    const int blk = blockIdx.x;

    if (tid < NDISC) {
        // =============== warps 0-11: worklist-BFS discovery ===============
        for (int i = tid; i < HSZ; i += NDISC) hkey[i] = -1;
        for (int i = tid; i < NINT / 32; i += NDISC) bits[i] = 0u;
        BAR1();
        if (tid == 0) {
            for (int l = 0; l < LEVELS; ++l) slcnt[l] = 0;
            scnt = 1; sFail = 0;
            porig[0] = TOTAL - 1;                  // root = plan idx (cid) 0
            meta[0]  = (11 << 16) | 0;
            slcnt[11] = 1;
        }
        BAR1();

        int s = 0, e = 1;
        while (s < e) {
            for (int i = s + tid; i < e; i += NDISC) {
                const int ni = porig[i] - LEAVES;
                const int4 ch = ((const int4*)child_idx)[ni];
                pch[i] = ch;
                pop[i] = (unsigned char)op_type[ni];
                const int cs[4] = {ch.x, ch.y, ch.z, ch.w};
                #pragma unroll
                for (int f = 0; f < 4; ++f) {
                    const int c = cs[f];
                    if (c < LEAVES) continue;
                    const int ci = c - LEAVES;
                    const unsigned int m = 1u << (ci & 31);
                    const unsigned int old = atomicOr(&bits[ci >> 5], m);
                    if (!(old & m)) {                         // we claimed c
                        const int cid = atomicAdd(&scnt, 1);
                        if (cid >= PCAP) { sFail = 1; continue; }
                        porig[cid] = c;
                        const int l2 = ci >> 12;              // / WIDTH
                        const int r2 = atomicAdd(&slcnt[l2], 1);
                        meta[cid] = (l2 << 16) | r2;
                        // write-only hash insert (lookups happen post-bar)
                        unsigned slot = ((unsigned)c * 2654435761u) & (HSZ - 1);
                        while (atomicCAS(&hkey[slot], -1, c) != -1)
                            slot = (slot + 1) & (HSZ - 1);
                        hval[slot] = (unsigned short)cid;
                    }
                }
            }
            BAR1();                                   // appends of this wave done
            if (tid == 0) { sE = (scnt < PCAP) ? scnt : PCAP; sF = sFail; }
            BAR1();                                   // snapshot stable
            s = e; e = sE;
            if (sF) break;
        }
    } else {
        // =============== warps 12-15: stage x rows into smem ===============
        for (int idx = tid - NDISC; idx < (BBK * NUM_VARS) / 4; idx += NTHR - NDISC) {
            const int r  = idx >> 9;                  // /512 float4 per row
            const int c4 = idx & 511;
            const float4 v =
                ((const float4*)x)[(size_t)(blk * BBK + r) * (NUM_VARS / 4) + c4];
            *(float4*)&xrow[r * XPAD + c4 * 4] = v;
        }
    }
    __syncthreads();   // join: discovery + staging complete

    const int bb = tid & (BBK - 1);

    if (sF) {
        // =============== dense fallback (worst case only) ===============
        for (int l = 0; l < LEVELS; ++l) {
            for (int k = tid; k < WIDTH * BBK; k += NTHR) {
                const int w = k >> 3, b2 = k & 7, bg2 = blk * BBK + b2;
                const int ni = l * WIDTH + w;
                const int4 ch = ((const int4*)child_idx)[ni];
                const int cs[4] = {ch.x, ch.y, ch.z, ch.w};
                float v[4];
                #pragma unroll
                for (int f = 0; f < 4; ++f) {
                    const int c = cs[f];
                    if (c < LEAVES) {
                        const float xv = xrow[b2 * XPAD + (c & (NUM_VARS - 1))];
                        v[f] = (c < NUM_VARS) ? xv : 1.0f - xv;
                    } else {
                        v[f] = g_dense[(size_t)(c - LEAVES) * B + bg2];
                    }
                }
                const float r = op_type[ni] ? (v[0] + v[1]) + (v[2] + v[3])
                                            : (v[0] * v[1]) * (v[2] * v[3]);
                g_dense[(size_t)ni * B + bg2] = r;
            }
            __syncthreads();
        }
        if (tid < BBK)
            out[blk * BBK + tid] = g_dense[(size_t)(NINT - 1) * B + blk * BBK + tid];
        return;
    }

    // ---- prefix offsets for level-sorted plan ----
    if (tid == 0) {
        int o = 0;
        for (int l = 0; l < LEVELS; ++l) { soff[l] = o; o += slcnt[l]; }
        soff[LEVELS] = o;
    }
    __syncthreads();

    // ---- resolution: encode + scatter entries into level order ----
    // 16-bit operand field: bit15 = leaf, bits0-11 = leaf id or cid.
    // op stored in bit14 of field0. Entry's own cid recorded in scid[].
    const int n = sE;
    for (int i = tid; i < n; i += NTHR) {
        const int4 ch = pch[i];
        const int mt = meta[i];
        const int j  = soff[mt >> 16] + (mt & 0xFFFF);
        unsigned f[4];
        const int cs[4] = {ch.x, ch.y, ch.z, ch.w};
        #pragma unroll
        for (int q = 0; q < 4; ++q) {
            const int c = cs[q];
            if (c < LEAVES) f[q] = 0x8000u | (unsigned)c;
            else {
                unsigned slot = ((unsigned)c * 2654435761u) & (HSZ - 1);
                while (hkey[slot] != c) slot = (slot + 1) & (HSZ - 1);
                f[q] = hval[slot];
            }
        }
        f[0] |= ((unsigned)pop[i] & 1u) << 14;
        sch[j]  = make_int2((int)(f[0] | (f[1] << 16)), (int)(f[2] | (f[3] << 16)));
        scid[j] = (unsigned short)i;
    }
    __syncthreads();

    // =============== forward: 12 short all-SMEM level phases ===============
    const int lane = tid >> 3;                        // 0..63

    for (int l = 0; l < LEVELS; ++l) {
        const int s0 = soff[l], e0 = soff[l + 1];
        for (int i = s0 + lane; i < e0; i += NTHR / BBK) {
            const int2 e = sch[i];
            const unsigned f0 = (unsigned)e.x & 0xFFFFu;
            const unsigned f1 = (unsigned)e.x >> 16;
            const unsigned f2 = (unsigned)e.y & 0xFFFFu;
            const unsigned f3 = (unsigned)e.y >> 16;
            const int op = (f0 >> 14) & 1;
            #define FETCH(ff) (((ff) & 0x8000u)                                  \
                ? (((ff) & 2048u)                                                \
                    ? 1.0f - xrow[bb * XPAD + (int)((ff) & 2047u)]               \
                    :        xrow[bb * XPAD + (int)((ff) & 2047u)])              \
                : val[(int)((ff) & 0xFFFu) * VPAD + bb])
            const float v0 = FETCH(f0 & 0x8FFFu);
            const float v1 = FETCH(f1);
            const float v2 = FETCH(f2);
            const float v3 = FETCH(f3);
            #undef FETCH
            const float r = op ? (v0 + v1) + (v2 + v3)
                               : (v0 * v1) * (v2 * v3);
            val[(int)scid[i] * VPAD + bb] = r;
        }
        __syncthreads();
    }

    if (tid < BBK) out[blk * BBK + tid] = val[tid];   // root cid = 0

}

// ---------------------------------------------------------------------------
// Launch: x (f32), child_idx (i32), op_type (i32). One kernel; capturable.
// ---------------------------------------------------------------------------
extern "C" void kernel_launch(void* const* d_in, const int* in_sizes, int n_in,
                              void* d_out, int out_size) {
    const float* x         = (const float*)d_in[0];
    const int*   child_idx = (const int*)  d_in[1];
    const int*   op_type   = (const int*)  d_in[2];
    float*       out       = (float*)d_out;

    cudaFuncSetAttribute(eval_all,
                         cudaFuncAttributeMaxDynamicSharedMemorySize, SM_TOTAL);
    eval_all<<<NBLK, NTHR, SM_TOTAL>>>(x, child_idx, op_type, out);
}